// round 5
// baseline (speedup 1.0000x reference)
#include <cuda_runtime.h>
#include <cstdint>
#include <cstddef>

#define B_ 2
#define H_ 8
#define NN 384
#define DD 64
#define TI 2
#define JT 4
#define NTH 256
#define NTILES (NN/JT)

// shared memory layout (float offsets)
#define SE_STRIDE 4352                    // JT * TI * 8 * 68
#define SK_STRIDE 2176                    // JT * 8 * 68
#define ES_OFF 0                          // Es[2][SE_STRIDE]
#define KS_OFF (2*SE_STRIDE)              // Ks[2][SK_STRIDE]
#define VS_OFF (KS_OFF + 2*SK_STRIDE)     // Vs[2][SK_STRIDE]
#define MSK_OFF (VS_OFF + 2*SK_STRIDE)
#define FLG_OFF (MSK_OFF + NN)
#define SMEM_FLOATS (FLG_OFF + 8)
#define CTX ((size_t)B_*H_*NN*DD)

__device__ __forceinline__ float ex2(float x){ float r; asm("ex2.approx.f32 %0,%1;":"=f"(r):"f"(x)); return r; }
__device__ __forceinline__ void cp16(uint32_t d, const void* s){
    asm volatile("cp.async.ca.shared.global [%0], [%1], 16;"::"r"(d),"l"(s));
}
__device__ __forceinline__ void cpcommit(){ asm volatile("cp.async.commit_group;"); }
__device__ __forceinline__ void cpwait0(){ asm volatile("cp.async.wait_group 0;"); }

__device__ __forceinline__ float dot8(const float* q, float4 a, float4 b){
    float s = q[0]*a.x;
    s=fmaf(q[1],a.y,s); s=fmaf(q[2],a.z,s); s=fmaf(q[3],a.w,s);
    s=fmaf(q[4],b.x,s); s=fmaf(q[5],b.y,s); s=fmaf(q[6],b.z,s); s=fmaf(q[7],b.w,s);
    return s;
}

// ---------------------------------------------------------------------------
// One CTA = (b, 2 consecutive i rows), all 8 heads (warp = head).
// Lane l: js = l>>3 selects one of 4 j's per tile, dc = l&7 selects 8-d chunk.
// E: LDG->reg->scatter-STS, double-buffered. K/V: cp.async 2-stage ring.
// Smem planes padded with off(d) = d + (d>=32)*4 -> conflict-free STS and LDS.
// Epilogue: context writes + in-place attn softmax normalization (no 2nd kernel).
// ---------------------------------------------------------------------------
__global__ __launch_bounds__(NTH,3)
void attn_main(const float* __restrict__ Q, const float* __restrict__ Kg,
               const float* __restrict__ Vg, const unsigned char* __restrict__ Mraw,
               const float* __restrict__ E, float* __restrict__ out)
{
    extern __shared__ float sm[];
    int* msk = (int*)(sm + MSK_OFF);
    int* flg = (int*)(sm + FLG_OFF);
    const int t=threadIdx.x, h=t>>5, l=t&31, js=l>>3, dc=l&7;
    const int i0=blockIdx.x*TI, b=blockIdx.y;
    const uint32_t smb = (uint32_t)__cvta_generic_to_shared(sm);

    // --- mask dtype detect (u8 / i32 / f32 bool) + stage this b's mask -----
    if (t<2) flg[t]=0;
    __syncthreads();
    for (int i=t;i<B_*NN;i+=NTH){
        unsigned char v=Mraw[i];
        if(v){ if(i&3) flg[0]=1; if(((i&3)==3)&&v==0x3F) flg[1]=1; }
    }
    __syncthreads();
    {
        int mode = flg[1]?2:(flg[0]?1:0);
        for (int j=t;j<NN;j+=NTH){
            int idx=b*NN+j, m;
            if(mode==2)      m=(((const float*)Mraw)[idx]!=0.f);
            else if(mode==1) m=(Mraw[idx]!=0);
            else             m=(((const int*)Mraw)[idx]!=0);
            msk[j]=m;
        }
    }

    // --- Q into registers: q[ii][8 d-chunk floats] -------------------------
    float qv[TI][8];
#pragma unroll
    for(int ii=0;ii<TI;ii++){
        const float4* qp=(const float4*)Q + ((size_t)((b*H_+h)*NN + i0+ii))*16 + dc*2;
        float4 a=qp[0], bb=qp[1];
        qv[ii][0]=a.x; qv[ii][1]=a.y; qv[ii][2]=a.z; qv[ii][3]=a.w;
        qv[ii][4]=bb.x;qv[ii][5]=bb.y;qv[ii][6]=bb.z;qv[ii][7]=bb.w;
    }

    // --- KV staging (cp.async): thread -> (tensor, js, h, d4) chunks -------
    const int jsk=t>>7, hk=(t>>4)&7, d4=t&15;
    const char* pK=(const char*)Kg + (((size_t)(b*H_+hk))*NN + jsk)*256 + d4*16;
    const char* pV=(const char*)Vg + (((size_t)(b*H_+hk))*NN + jsk)*256 + d4*16;
    const int dK0 = KS_OFF + (jsk*8+hk)*68 + d4*4 + ((d4>>3)<<2);

    // --- E staging: thread -> (ii, g) float4 chunk, js varies per load -----
    const int g=t&127, iiE=t>>7;
    const float4* pE=(const float4*)E + (((size_t)(b*NN + i0+iiE))*NN)*128 + g;
    const int dE = g>>1, h0=(g&1)*4;
    const int sE0 = ES_OFF + (iiE*8+h0)*68 + dE + ((dE>>5)<<2);

    // --- accumulators ------------------------------------------------------
    float a1[TI][8], a2[TI][8], l1[TI], l2[TI];
#pragma unroll
    for(int ii=0;ii<TI;ii++){
        l1[ii]=0.f; l2[ii]=0.f;
#pragma unroll
        for(int m=0;m<8;m++){ a1[ii][m]=0.f; a2[ii][m]=0.f; }
    }

    float* attn0 = out + 2*CTX + ((size_t)((b*H_+h)*NN)+i0)*NN;

    const float Cc   = 0.18033688011112042f;      // SCALE * log2(e)
    const float NEGT = -1.4426950408889634e9f;    // -1e9 * log2(e)

    // --- prologue: KV tile 0 async into stage 0; E tile 0 into regs --------
    {
        uint32_t dk = smb + (uint32_t)dK0*4u;
        cp16(dk, pK);            cp16(dk+1088u*4u, pK+512);
        cp16(dk+(uint32_t)(VS_OFF-KS_OFF)*4u, pV);
        cp16(dk+(uint32_t)(VS_OFF-KS_OFF+1088)*4u, pV+512);
        cpcommit();
        pK+=1024; pV+=1024;
    }
    float4 er[JT];
#pragma unroll
    for(int jj=0;jj<JT;jj++) er[jj]=pE[jj*128];
    pE+=512;

    for (int it=0; it<NTILES; ++it){
        const int st = it&1;
        // STS E tile it into Es[st] (conflict-free scalar scatter)
        {
            float* bp = sm + sE0 + st*SE_STRIDE;
#pragma unroll
            for(int jj=0;jj<JT;jj++){
                float* p = bp + jj*1088;
                p[0]=er[jj].x; p[68]=er[jj].y; p[136]=er[jj].z; p[204]=er[jj].w;
            }
        }
        if (it+1<NTILES){
#pragma unroll
            for(int jj=0;jj<JT;jj++) er[jj]=pE[jj*128];
            pE+=512;
        }
        cpwait0();              // KV tile 'it' landed
        __syncthreads();        // all STS + KV visible; stage st^1 free
        if (it+1<NTILES){       // issue KV tile it+1 into stage st^1
            uint32_t dk = smb + (uint32_t)(dK0 + (st^1)*SK_STRIDE)*4u;
            cp16(dk, pK);            cp16(dk+1088u*4u, pK+512);
            cp16(dk+(uint32_t)(VS_OFF-KS_OFF)*4u, pV);
            cp16(dk+(uint32_t)(VS_OFF-KS_OFF+1088)*4u, pV+512);
            cpcommit();
            pK+=1024; pV+=1024;
        }

        // ---- compute tile it ---------------------------------------------
        {
            const float* eb = sm + ES_OFF + st*SE_STRIDE
                              + ((js*TI)*8 + h)*68 + dc*8 + ((dc>>2)<<2);
            float4 e0a = ((const float4*)eb)[0], e0b = ((const float4*)eb)[1];
            float4 e1a = ((const float4*)(eb+544))[0], e1b = ((const float4*)(eb+544))[1];
            const float* kp = sm + KS_OFF + st*SK_STRIDE
                              + (js*8+h)*68 + dc*8 + ((dc>>2)<<2);
            float4 ka=((const float4*)kp)[0], kb=((const float4*)kp)[1];
            const float* vp = kp + (VS_OFF-KS_OFF);
            float4 va=((const float4*)vp)[0], vb=((const float4*)vp)[1];

            float pk0=dot8(qv[0],ka,kb),  pk1=dot8(qv[1],ka,kb);
            float pe0=dot8(qv[0],e0a,e0b),pe1=dot8(qv[1],e1a,e1b);
#pragma unroll
            for(int o=1;o<8;o<<=1){
                pk0+=__shfl_xor_sync(0xffffffffu,pk0,o);
                pk1+=__shfl_xor_sync(0xffffffffu,pk1,o);
                pe0+=__shfl_xor_sync(0xffffffffu,pe0,o);
                pe1+=__shfl_xor_sync(0xffffffffu,pe1,o);
            }
            const int mj = msk[it*JT+js];
            float vf[8]={va.x,va.y,va.z,va.w,vb.x,vb.y,vb.z,vb.w};
            float e0f[8]={e0a.x,e0a.y,e0a.z,e0a.w,e0b.x,e0b.y,e0b.z,e0b.w};
            float e1f[8]={e1a.x,e1a.y,e1a.z,e1a.w,e1b.x,e1b.y,e1b.z,e1b.w};

            float t2 = mj ? NEGT : pk0*Cc;
            float t1 = mj ? NEGT : (pk0+pe0)*Cc;
            float p1 = ex2(t1), p2 = ex2(t2);
            l1[0]+=p1; l2[0]+=p2;
#pragma unroll
            for(int m=0;m<8;m++){
                a1[0][m]=fmaf(p1, vf[m]+e0f[m], a1[0][m]);
                a2[0][m]=fmaf(p2, vf[m],        a2[0][m]);
            }
            if(dc==0) attn0[it*JT+js]=t2;

            t2 = mj ? NEGT : pk1*Cc;
            t1 = mj ? NEGT : (pk1+pe1)*Cc;
            p1 = ex2(t1); p2 = ex2(t2);
            l1[1]+=p1; l2[1]+=p2;
#pragma unroll
            for(int m=0;m<8;m++){
                a1[1][m]=fmaf(p1, vf[m]+e1f[m], a1[1][m]);
                a2[1][m]=fmaf(p2, vf[m],        a2[1][m]);
            }
            if(dc==0) attn0[NN + it*JT+js]=t2;
        }
    }

    // --- epilogue: reduce across the 4 js groups (offsets 8,16) ------------
#pragma unroll
    for(int o=8;o<32;o<<=1){
#pragma unroll
        for(int ii=0;ii<TI;ii++){
            l1[ii]+=__shfl_xor_sync(0xffffffffu,l1[ii],o);
            l2[ii]+=__shfl_xor_sync(0xffffffffu,l2[ii],o);
#pragma unroll
            for(int m=0;m<8;m++){
                a1[ii][m]+=__shfl_xor_sync(0xffffffffu,a1[ii][m],o);
                a2[ii][m]+=__shfl_xor_sync(0xffffffffu,a2[ii][m],o);
            }
        }
    }
#pragma unroll
    for(int ii=0;ii<TI;ii++){
        float inv1=1.0f/l1[ii], inv2=1.0f/l2[ii];
        if(l<8){   // js==0 lanes, dc=l
            size_t o=((size_t)((b*H_+h)*NN)+i0+ii)*DD + (size_t)dc*8;
            float4* op=(float4*)(out+o);
            op[0]=make_float4(a1[ii][0]*inv1,a1[ii][1]*inv1,a1[ii][2]*inv1,a1[ii][3]*inv1);
            op[1]=make_float4(a1[ii][4]*inv1,a1[ii][5]*inv1,a1[ii][6]*inv1,a1[ii][7]*inv1);
            float4* op2=(float4*)(out+CTX+o);
            op2[0]=make_float4(a2[ii][0]*inv2,a2[ii][1]*inv2,a2[ii][2]*inv2,a2[ii][3]*inv2);
            op2[1]=make_float4(a2[ii][4]*inv2,a2[ii][5]*inv2,a2[ii][6]*inv2,a2[ii][7]*inv2);
        }
    }

    // --- fused attn normalization: re-read this warp's rows, exp2, scale ---
    // Block-local global writes are visible after __syncthreads(); each warp
    // only touches rows written by its own lanes.
    __syncthreads();
#pragma unroll
    for(int ii=0;ii<TI;ii++){
        float inv2 = 1.0f/l2[ii];
        float* row = attn0 + (size_t)ii*NN;
#pragma unroll
        for(int jj=0;jj<NN/32;jj++){
            int j = jj*32 + l;
            row[j] = ex2(row[j])*inv2;
        }
    }
}

extern "C" void kernel_launch(void* const* d_in, const int* in_sizes, int n_in,
                              void* d_out, int out_size)
{
    const float* Q = (const float*)d_in[0];
    const float* K = (const float*)d_in[1];
    const float* V = (const float*)d_in[2];
    const unsigned char* M = (const unsigned char*)d_in[3];
    const float* E = (const float*)d_in[4];
    float* out = (float*)d_out;

    size_t smemB = (size_t)SMEM_FLOATS * 4;
    cudaFuncSetAttribute(attn_main, cudaFuncAttributeMaxDynamicSharedMemorySize, (int)smemB);
    dim3 grid(NN/TI, B_);
    attn_main<<<grid, NTH, smemB>>>(Q, K, V, M, E, out);
}

// round 6
// speedup vs baseline: 1.8448x; 1.8448x over previous
#include <cuda_runtime.h>
#include <cstdint>
#include <cstddef>

#define B_ 2
#define H_ 8
#define NN 384
#define DD 64
#define TI 2
#define JT 4
#define NTH 256
#define NTILES (NN/JT)

// shared memory layout (float offsets)
#define SE_STRIDE 4352                    // JT * TI * 8 * 68
#define SK_STRIDE 2176                    // JT * 8 * 68
#define ES_OFF 0                          // Es[2][SE_STRIDE]
#define KS_OFF (2*SE_STRIDE)              // Ks[3][SK_STRIDE]
#define VS_OFF (KS_OFF + 3*SK_STRIDE)     // Vs[3][SK_STRIDE]
#define MSK_OFF (VS_OFF + 3*SK_STRIDE)
#define FLG_OFF (MSK_OFF + NN)
#define SMEM_FLOATS (FLG_OFF + 8)
#define CTX ((size_t)B_*H_*NN*DD)

__device__ __forceinline__ float ex2(float x){ float r; asm("ex2.approx.f32 %0,%1;":"=f"(r):"f"(x)); return r; }
__device__ __forceinline__ void cp16(uint32_t d, const void* s){
    asm volatile("cp.async.ca.shared.global [%0], [%1], 16;"::"r"(d),"l"(s));
}
__device__ __forceinline__ void cpcommit(){ asm volatile("cp.async.commit_group;"); }
__device__ __forceinline__ void cpwait1(){ asm volatile("cp.async.wait_group 1;"); }

__device__ __forceinline__ float dot8(const float* q, float4 a, float4 b){
    float s = q[0]*a.x;
    s=fmaf(q[1],a.y,s); s=fmaf(q[2],a.z,s); s=fmaf(q[3],a.w,s);
    s=fmaf(q[4],b.x,s); s=fmaf(q[5],b.y,s); s=fmaf(q[6],b.z,s); s=fmaf(q[7],b.w,s);
    return s;
}

// ---------------------------------------------------------------------------
// One CTA = (b, 2 consecutive i rows), all 8 heads (warp = head).
// Lane l: js = l>>3 selects one of 4 j's per tile, dc = l&7 selects 8-d chunk.
// E: LDG->reg->scatter-STS, double-buffered. K/V: cp.async 3-stage ring.
// Smem planes padded with off(d) = d + (d>=32)*4 -> conflict-free STS and LDS.
// Occupancy 2 (128-reg budget) -- NO spills (the occ-3 variant spilled at 80
// regs and regressed: L1 60.6% of it spill LDL/STL).
// Epilogue: context writes + in-place attn softmax normalization (fused).
// ---------------------------------------------------------------------------
__global__ __launch_bounds__(NTH,2)
void attn_main(const float* __restrict__ Q, const float* __restrict__ Kg,
               const float* __restrict__ Vg, const unsigned char* __restrict__ Mraw,
               const float* __restrict__ E, float* __restrict__ out)
{
    extern __shared__ float sm[];
    int* msk = (int*)(sm + MSK_OFF);
    int* flg = (int*)(sm + FLG_OFF);
    const int t=threadIdx.x, h=t>>5, l=t&31, js=l>>3, dc=l&7;
    const int i0=blockIdx.x*TI, b=blockIdx.y;
    const uint32_t smb = (uint32_t)__cvta_generic_to_shared(sm);

    // --- mask dtype detect (u8 / i32 / f32 bool) + stage this b's mask -----
    if (t<2) flg[t]=0;
    __syncthreads();
    for (int i=t;i<B_*NN;i+=NTH){
        unsigned char v=Mraw[i];
        if(v){ if(i&3) flg[0]=1; if(((i&3)==3)&&v==0x3F) flg[1]=1; }
    }
    __syncthreads();
    {
        int mode = flg[1]?2:(flg[0]?1:0);
        for (int j=t;j<NN;j+=NTH){
            int idx=b*NN+j, m;
            if(mode==2)      m=(((const float*)Mraw)[idx]!=0.f);
            else if(mode==1) m=(Mraw[idx]!=0);
            else             m=(((const int*)Mraw)[idx]!=0);
            msk[j]=m;
        }
    }

    // --- Q into registers: q[ii][8 d-chunk floats] -------------------------
    float qv[TI][8];
#pragma unroll
    for(int ii=0;ii<TI;ii++){
        const float4* qp=(const float4*)Q + ((size_t)((b*H_+h)*NN + i0+ii))*16 + dc*2;
        float4 a=qp[0], bb=qp[1];
        qv[ii][0]=a.x; qv[ii][1]=a.y; qv[ii][2]=a.z; qv[ii][3]=a.w;
        qv[ii][4]=bb.x;qv[ii][5]=bb.y;qv[ii][6]=bb.z;qv[ii][7]=bb.w;
    }

    // --- KV staging (cp.async): thread -> (tensor, js, h, d4) chunks -------
    const int jsk=t>>7, hk=(t>>4)&7, d4=t&15;
    const char* pK=(const char*)Kg + (((size_t)(b*H_+hk))*NN + jsk)*256 + d4*16;
    const char* pV=(const char*)Vg + (((size_t)(b*H_+hk))*NN + jsk)*256 + d4*16;
    const int dK0 = KS_OFF + (jsk*8+hk)*68 + d4*4 + ((d4>>3)<<2);

    // --- E staging: thread -> (ii, g) float4 chunk, js varies per load -----
    const int g=t&127, iiE=t>>7;
    const float4* pE=(const float4*)E + (((size_t)(b*NN + i0+iiE))*NN)*128 + g;
    const int dE = g>>1, h0=(g&1)*4;
    const int sE0 = ES_OFF + (iiE*8+h0)*68 + dE + ((dE>>5)<<2);

    // --- accumulators ------------------------------------------------------
    float a1[TI][8], a2[TI][8], l1[TI], l2[TI];
#pragma unroll
    for(int ii=0;ii<TI;ii++){
        l1[ii]=0.f; l2[ii]=0.f;
#pragma unroll
        for(int m=0;m<8;m++){ a1[ii][m]=0.f; a2[ii][m]=0.f; }
    }

    float* attn0 = out + 2*CTX + ((size_t)((b*H_+h)*NN)+i0)*NN;

    const float Cc   = 0.18033688011112042f;      // SCALE * log2(e)
    const float NEGT = -1.4426950408889634e9f;    // -1e9 * log2(e)

    // --- prologue: KV tiles 0,1 async; E tile 0 into regs ------------------
#pragma unroll
    for(int p=0;p<2;p++){
        uint32_t dk = smb + (uint32_t)(dK0 + p*SK_STRIDE)*4u;
        cp16(dk, pK);            cp16(dk+1088u*4u, pK+512);
        cp16(dk+(uint32_t)(VS_OFF-KS_OFF)*4u, pV);
        cp16(dk+(uint32_t)(VS_OFF-KS_OFF+1088)*4u, pV+512);
        cpcommit();
        pK+=1024; pV+=1024;
    }
    float4 er[JT];
#pragma unroll
    for(int jj=0;jj<JT;jj++) er[jj]=pE[jj*128];
    pE+=512;

    int skv=0, skv2=2;
    for (int it=0; it<NTILES; ++it){
        const int st = it&1;
        // STS E tile it into Es[st] (conflict-free scalar scatter)
        {
            float* bp = sm + sE0 + st*SE_STRIDE;
#pragma unroll
            for(int jj=0;jj<JT;jj++){
                float* p = bp + jj*1088;
                p[0]=er[jj].x; p[68]=er[jj].y; p[136]=er[jj].z; p[204]=er[jj].w;
            }
        }
        if (it+1<NTILES){
#pragma unroll
            for(int jj=0;jj<JT;jj++) er[jj]=pE[jj*128];
            pE+=512;
        }
        cpwait1();              // KV tile 'it' landed (one group may stay in flight)
        __syncthreads();        // all STS + all threads' KV visible
        if (it+2<NTILES){       // issue KV for tile it+2 (stage freed by barrier)
            uint32_t dk = smb + (uint32_t)(dK0 + skv2*SK_STRIDE)*4u;
            cp16(dk, pK);            cp16(dk+1088u*4u, pK+512);
            cp16(dk+(uint32_t)(VS_OFF-KS_OFF)*4u, pV);
            cp16(dk+(uint32_t)(VS_OFF-KS_OFF+1088)*4u, pV+512);
            pK+=1024; pV+=1024;
            if(++skv2==3) skv2=0;
        }
        cpcommit();

        // ---- compute tile it ---------------------------------------------
        {
            const float* eb = sm + ES_OFF + st*SE_STRIDE
                              + ((js*TI)*8 + h)*68 + dc*8 + ((dc>>2)<<2);
            float4 e0a = ((const float4*)eb)[0], e0b = ((const float4*)eb)[1];
            float4 e1a = ((const float4*)(eb+544))[0], e1b = ((const float4*)(eb+544))[1];
            const float* kp = sm + KS_OFF + skv*SK_STRIDE
                              + (js*8+h)*68 + dc*8 + ((dc>>2)<<2);
            float4 ka=((const float4*)kp)[0], kb=((const float4*)kp)[1];
            const float* vp = kp + (VS_OFF-KS_OFF);
            float4 va=((const float4*)vp)[0], vb=((const float4*)vp)[1];

            float pk0=dot8(qv[0],ka,kb),  pk1=dot8(qv[1],ka,kb);
            float pe0=dot8(qv[0],e0a,e0b),pe1=dot8(qv[1],e1a,e1b);
#pragma unroll
            for(int o=1;o<8;o<<=1){
                pk0+=__shfl_xor_sync(0xffffffffu,pk0,o);
                pk1+=__shfl_xor_sync(0xffffffffu,pk1,o);
                pe0+=__shfl_xor_sync(0xffffffffu,pe0,o);
                pe1+=__shfl_xor_sync(0xffffffffu,pe1,o);
            }
            const int mj = msk[it*JT+js];
            float vf[8]={va.x,va.y,va.z,va.w,vb.x,vb.y,vb.z,vb.w};
            float e0f[8]={e0a.x,e0a.y,e0a.z,e0a.w,e0b.x,e0b.y,e0b.z,e0b.w};
            float e1f[8]={e1a.x,e1a.y,e1a.z,e1a.w,e1b.x,e1b.y,e1b.z,e1b.w};

            float t2 = mj ? NEGT : pk0*Cc;
            float t1 = mj ? NEGT : (pk0+pe0)*Cc;
            float p1 = ex2(t1), p2 = ex2(t2);
            l1[0]+=p1; l2[0]+=p2;
#pragma unroll
            for(int m=0;m<8;m++){
                a1[0][m]=fmaf(p1, vf[m]+e0f[m], a1[0][m]);
                a2[0][m]=fmaf(p2, vf[m],        a2[0][m]);
            }
            if(dc==0) attn0[it*JT+js]=t2;

            t2 = mj ? NEGT : pk1*Cc;
            t1 = mj ? NEGT : (pk1+pe1)*Cc;
            p1 = ex2(t1); p2 = ex2(t2);
            l1[1]+=p1; l2[1]+=p2;
#pragma unroll
            for(int m=0;m<8;m++){
                a1[1][m]=fmaf(p1, vf[m]+e1f[m], a1[1][m]);
                a2[1][m]=fmaf(p2, vf[m],        a2[1][m]);
            }
            if(dc==0) attn0[NN + it*JT+js]=t2;
        }
        if(++skv==3) skv=0;
    }

    // --- epilogue: reduce across the 4 js groups (offsets 8,16) ------------
#pragma unroll
    for(int o=8;o<32;o<<=1){
#pragma unroll
        for(int ii=0;ii<TI;ii++){
            l1[ii]+=__shfl_xor_sync(0xffffffffu,l1[ii],o);
            l2[ii]+=__shfl_xor_sync(0xffffffffu,l2[ii],o);
#pragma unroll
            for(int m=0;m<8;m++){
                a1[ii][m]+=__shfl_xor_sync(0xffffffffu,a1[ii][m],o);
                a2[ii][m]+=__shfl_xor_sync(0xffffffffu,a2[ii][m],o);
            }
        }
    }
#pragma unroll
    for(int ii=0;ii<TI;ii++){
        float inv1=1.0f/l1[ii], inv2=1.0f/l2[ii];
        if(l<8){   // js==0 lanes, dc=l
            size_t o=((size_t)((b*H_+h)*NN)+i0+ii)*DD + (size_t)dc*8;
            float4* op=(float4*)(out+o);
            op[0]=make_float4(a1[ii][0]*inv1,a1[ii][1]*inv1,a1[ii][2]*inv1,a1[ii][3]*inv1);
            op[1]=make_float4(a1[ii][4]*inv1,a1[ii][5]*inv1,a1[ii][6]*inv1,a1[ii][7]*inv1);
            float4* op2=(float4*)(out+CTX+o);
            op2[0]=make_float4(a2[ii][0]*inv2,a2[ii][1]*inv2,a2[ii][2]*inv2,a2[ii][3]*inv2);
            op2[1]=make_float4(a2[ii][4]*inv2,a2[ii][5]*inv2,a2[ii][6]*inv2,a2[ii][7]*inv2);
        }
    }

    // --- fused attn normalization: re-read this warp's rows, exp2, scale ---
    // __syncthreads() orders block-local global writes; each warp reads only
    // rows written by its own lanes.
    __syncthreads();
#pragma unroll
    for(int ii=0;ii<TI;ii++){
        float inv2 = 1.0f/l2[ii];
        float* row = attn0 + (size_t)ii*NN;
#pragma unroll
        for(int jj=0;jj<NN/32;jj++){
            int j = jj*32 + l;
            row[j] = ex2(row[j])*inv2;
        }
    }
}

extern "C" void kernel_launch(void* const* d_in, const int* in_sizes, int n_in,
                              void* d_out, int out_size)
{
    const float* Q = (const float*)d_in[0];
    const float* K = (const float*)d_in[1];
    const float* V = (const float*)d_in[2];
    const unsigned char* M = (const unsigned char*)d_in[3];
    const float* E = (const float*)d_in[4];
    float* out = (float*)d_out;

    size_t smemB = (size_t)SMEM_FLOATS * 4;
    cudaFuncSetAttribute(attn_main, cudaFuncAttributeMaxDynamicSharedMemorySize, (int)smemB);
    dim3 grid(NN/TI, B_);
    attn_main<<<grid, NTH, smemB>>>(Q, K, V, M, E, out);
}